// round 14
// baseline (speedup 1.0000x reference)
#include <cuda_runtime.h>
#include <cuda_bf16.h>
#include <cstdint>

// Problem constants (fixed by the dataset): B=64, T=12, C=64, SIDE=32, S2=1024.
#define PB   64
#define PT   12
#define PC   64
#define PS2  1024
#define ROWS (PB * PC)            // 4096 (b,c) rows in the last-T slice

#define RPB    8                  // rows per block (both kernels)
#define GRIDA  (ROWS / RPB)       // 512
#define GRIDB  (ROWS / RPB)       // 512
#define NSHARD 16                 // mask atomic shards (512/16 = 32 RMW per address)
#define ROW_BYTES (PS2 * 4)       // 4 KB per row

// Persistent scratch (module-load zeroed; kernel B's last block re-zeroes the
// shards+counter each launch => every call identical => graph-replay safe).
__device__ int      g_poi[PS2];
__device__ unsigned g_maskpad[NSHARD * 32 * 64];  // word (k,i) at (k*32+i)*64
__device__ int      g_c1;                         // B epilogue counter

// ---- minimal PTX helpers -------------------------------------------------
__device__ __forceinline__ uint32_t smem_u32(const void* p) {
    uint32_t a;
    asm("{ .reg .u64 t; cvta.to.shared.u64 t, %1; cvt.u32.u64 %0, t; }"
        : "=r"(a) : "l"(p));
    return a;
}
__device__ __forceinline__ void mbar_init(uint32_t mbar, uint32_t cnt) {
    asm volatile("mbarrier.init.shared.b64 [%0], %1;" :: "r"(mbar), "r"(cnt) : "memory");
}
__device__ __forceinline__ void mbar_expect_tx(uint32_t mbar, uint32_t bytes) {
    asm volatile("mbarrier.arrive.expect_tx.shared.b64 _, [%0], %1;"
                 :: "r"(mbar), "r"(bytes) : "memory");
}
__device__ __forceinline__ void mbar_wait(uint32_t mbar, uint32_t parity) {
    asm volatile(
        "{\n\t"
        ".reg .pred P;\n\t"
        "WL_%=:\n\t"
        "mbarrier.try_wait.parity.acquire.cta.shared::cta.b64 P, [%0], %1, 0x989680;\n\t"
        "@P bra.uni WD_%=;\n\t"
        "bra.uni WL_%=;\n\t"
        "WD_%=:\n\t"
        "}" :: "r"(mbar), "r"(parity) : "memory");
}
__device__ __forceinline__ void bulk_ld(uint32_t sdst, const void* gsrc,
                                        uint32_t bytes, uint32_t mbar) {
    asm volatile(
        "cp.async.bulk.shared::cluster.global.mbarrier::complete_tx::bytes "
        "[%0], [%1], %2, [%3];"
        :: "r"(sdst), "l"(gsrc), "r"(bytes), "r"(mbar) : "memory");
}

// ---- Kernel A: mask reduce (bulk-async loads) + poi decode ---------------
__global__ void __launch_bounds__(256)
reduce_kernel(const int* __restrict__ m, const int* __restrict__ poi_words) {
    __shared__ alignas(16) int mb[RPB][PS2];      // 32 KB staged mask rows
    __shared__ alignas(8) unsigned long long mbar_s;
    __shared__ unsigned smask[32];
    __shared__ int sh_odd;

    const int t = threadIdx.x;                    // 0..255
    const int g = blockIdx.x;                     // 0..511
    const int start = g * RPB;
    const uint32_t mbar = smem_u32(&mbar_s);

    if (t == 0) { mbar_init(mbar, 1); sh_odd = 0; }
    if (t < 32) smask[t] = 0;
    __syncthreads();                              // mbar visible to all

    if (t == 0) {
        mbar_expect_tx(mbar, RPB * ROW_BYTES);
#pragma unroll
        for (int r = 0; r < RPB; r++) {
            const int R = start + r;
            const int b = R >> 6, c = R & 63;
            const size_t base = ((size_t)(b * PT + (PT - 1)) * PC + c) * PS2;
            bulk_ld(smem_u32(&mb[r][0]), m + base, ROW_BYTES, mbar);
        }
    }

    // block 0: poi decode overlaps the bulk loads (dtype auto-detect; JAX
    // silently narrows jnp.int64 -> int32). First 1024 words safe either way;
    // int64 little-endian, values < 1024 => all odd words zero.
    int4 w = make_int4(0, 0, 0, 0), p0 = w, p1 = w;
    if (g == 0) {
        w  = ((const int4*)poi_words)[t];
        p0 = ((const int4*)poi_words)[2 * t];
        p1 = ((const int4*)poi_words)[2 * t + 1];
        if (w.y | w.w) atomicOr(&sh_odd, 1);
    }
    __syncthreads();                              // sh_odd + smask final
    if (g == 0) {
        ((int4*)g_poi)[t] = sh_odd ? w : make_int4(p0.x, p0.z, p1.x, p1.z);
    }

    mbar_wait(mbar, 0);                           // mask rows in smem

    int4 acc = make_int4(0, 0, 0, 0);
#pragma unroll
    for (int r = 0; r < RPB; r++) {
        const int4 v = ((const int4*)mb[r])[t];   // conflict-free LDS.128
        acc.x |= v.x; acc.y |= v.y; acc.z |= v.z; acc.w |= v.w;
    }
    const unsigned nib = (acc.x ? 1u : 0u) | (acc.y ? 2u : 0u)
                       | (acc.z ? 4u : 0u) | (acc.w ? 8u : 0u);
    if (nib) atomicOr(&smask[t >> 3], nib << ((t & 7) * 4));
    __syncthreads();
    if (t < 32 && smask[t])
        atomicOr(&g_maskpad[(((g & (NSHARD - 1)) * 32 + t) << 6)], smask[t]);
}

// ---- Kernel B: apply (bulk-async loads, predicated LDS gather, STG) ------
__global__ void __launch_bounds__(256)
apply_kernel(const float* __restrict__ d, float* __restrict__ out) {
    __shared__ alignas(16) float buf[RPB][PS2];   // 32 KB staged d rows
    __shared__ alignas(8) unsigned long long mbar_s;
    __shared__ unsigned smw[32];
    __shared__ int sh_last;

    const int t = threadIdx.x;
    const int g = blockIdx.x;
    const int start = g * RPB;
    const uint32_t mbar = smem_u32(&mbar_s);

    if (t == 0) { mbar_init(mbar, 1); sh_last = 0; }
    __syncthreads();

    if (t == 0) {
        mbar_expect_tx(mbar, RPB * ROW_BYTES);
#pragma unroll
        for (int r = 0; r < RPB; r++) {
            const int R = start + r;
            const int b = R >> 6, c = R & 63;
            const size_t base = ((size_t)(b * PT + (PT - 1)) * PC + c) * PS2;
            bulk_ld(smem_u32(&buf[r][0]), d + base, ROW_BYTES, mbar);
        }
    }

    // while TMA flies: combine mask shards + fetch poi (all L2-hot, written by A)
    if (t < 32) {
        unsigned x = 0;
#pragma unroll
        for (int k = 0; k < NSHARD; k++)
            x |= ((const volatile unsigned*)g_maskpad)[((k * 32 + t) << 6)];
        smw[t] = x;
    }
    const int4 pi = ((const int4*)g_poi)[t];      // cells 4t..4t+3
    __syncthreads();                              // smw ready
    const unsigned nib = (smw[t >> 3] >> ((t & 7) * 4)) & 0xFu;  // 1 = nonzero

    mbar_wait(mbar, 0);                           // d rows in smem

#pragma unroll
    for (int r = 0; r < RPB; r++) {
        float4 v = ((const float4*)buf[r])[t];    // direct term (LDS.128)
        if (!(nib & 1u)) v.x += buf[r][pi.x];     // predicated gathers
        if (!(nib & 2u)) v.y += buf[r][pi.y];
        if (!(nib & 4u)) v.z += buf[r][pi.z];
        if (!(nib & 8u)) v.w += buf[r][pi.w];
        ((float4*)(out + (size_t)(start + r) * PS2))[t] = v;
    }

    // epilogue: last block re-zeroes shards + counter for the next replay
    if (t == 0) {
        __threadfence();
        if (atomicAdd(&g_c1, 1) == GRIDB - 1) sh_last = 1;
    }
    __syncthreads();
    if (sh_last) {
        for (int i = t; i < NSHARD * 32; i += 256) g_maskpad[i << 6] = 0;
        if (t == 0) { g_c1 = 0; __threadfence(); }
    }
}

extern "C" void kernel_launch(void* const* d_in, const int* in_sizes, int n_in,
                              void* d_out, int out_size) {
    const float* d   = (const float*)d_in[0];
    const int*   m   = (const int*)d_in[1];
    const int*   poi = (const int*)d_in[2];   // int32 or int64 words, auto-detected
    // d_in[3] = side (constant 32), unused.
    float* out = (float*)d_out;

    reduce_kernel<<<GRIDA, 256>>>(m, poi);
    apply_kernel<<<GRIDB, 256>>>(d, out);
}

// round 15
// speedup vs baseline: 1.1335x; 1.1335x over previous
#include <cuda_runtime.h>
#include <cuda_bf16.h>
#include <cstdint>

// Problem constants (fixed by the dataset): B=64, T=12, C=64, SIDE=32, S2=1024.
#define PB   64
#define PT   12
#define PC   64
#define PS2  1024
#define ROWS (PB * PC)            // 4096 (b,c) rows in the last-T slice

#define RPB    8                  // rows per block (main)
#define GRIDM  (ROWS / RPB)       // 512 main blocks
#define NSHARD 16                 // mask atomic shards (512/16 = 32 RMW per address)
#define GRIDF  64                 // fixup blocks (64 x 64 rows = 4096)

// Persistent scratch (module-load zeroed; fixup's last block re-zeroes each
// launch => every call identical => graph-replay deterministic).
__device__ unsigned g_maskpad[NSHARD * 32 * 64];  // word (k,i) at (k*32+i)*64
__device__ int      g_c1;                         // fixup epilogue counter

// ---- Main kernel: speculative apply + mask reduce (no cross-block wait) ----
// out[row,s] = d[row,s] + (s even ? d[row,poi[s]] : 0)   [the guess]
// and publishes the TRUE per-cell nonzero mask to g_maskpad for verification.
__global__ void __launch_bounds__(256, 4)
main_kernel(const float* __restrict__ d, const int* __restrict__ m,
            const int* __restrict__ poi_words, float* __restrict__ out) {
    __shared__ float    rs[RPB][PS2];     // 32 KB staged d rows
    __shared__ unsigned smask[32];        // block-partial 1024-bit nonzero mask
    __shared__ int      sh_odd;

    const int t = threadIdx.x;            // 0..255
    const int g = blockIdx.x;             // 0..511
    const int row0 = g * RPB;
    const int b  = row0 >> 6;
    const int cc = row0 & 63;
    const size_t base = ((size_t)(b * PT + (PT - 1)) * PC + cc) * PS2;

    if (t == 0) sh_odd = 0;
    if (t < 32) smask[t] = 0;

    // ---- TRUE mask reduce over this block's 8 m rows (cells 4t..4t+3) ----
    const int* msrc = m + base;
    int4 acc = make_int4(0, 0, 0, 0);
#pragma unroll
    for (int r = 0; r < RPB; r++) {
        const int4 v = *(const int4*)(msrc + r * PS2 + 4 * t);
        acc.x |= v.x; acc.y |= v.y; acc.z |= v.z; acc.w |= v.w;
    }

    // ---- poi decode (every block; dtype auto-detect: JAX silently narrows
    // jnp.int64 -> int32). First 1024 words safe for both dtypes; int64
    // little-endian with values < 1024 => all odd words zero.
    const int4 w  = ((const int4*)poi_words)[t];
    const int4 p0 = ((const int4*)poi_words)[2 * t];
    const int4 p1 = ((const int4*)poi_words)[2 * t + 1];
    if (w.y | w.w) atomicOr(&sh_odd, 1);

    // ---- stage this block's 8 d rows into smem ----
    const float* dsrc = d + base;
    float4 v[RPB];
#pragma unroll
    for (int r = 0; r < RPB; r++)
        v[r] = *(const float4*)(dsrc + r * PS2 + 4 * t);
#pragma unroll
    for (int r = 0; r < RPB; r++)
        ((float4*)rs[r])[t] = v[r];

    __syncthreads();                      // rs staged, sh_odd + smask ready
    const int4 pi = sh_odd ? w : make_int4(p0.x, p0.z, p1.x, p1.z);

    const unsigned nib = (acc.x ? 1u : 0u) | (acc.y ? 2u : 0u)
                       | (acc.z ? 4u : 0u) | (acc.w ? 8u : 0u);
    if (nib) atomicOr(&smask[t >> 3], nib << ((t & 7) * 4));
    __syncthreads();                      // smask final
    if (t < 32 && smask[t])
        atomicOr(&g_maskpad[(((g & (NSHARD - 1)) * 32 + t) << 6)], smask[t]);

    // ---- speculative output: even cells (4t, 4t+2) get the compensation ----
#pragma unroll
    for (int r = 0; r < RPB; r++) {
        float4 x = v[r];
        x.x += rs[r][pi.x];               // cell 4t   (even -> guessed empty)
        x.z += rs[r][pi.z];               // cell 4t+2 (even -> guessed empty)
        ((float4*)(out + (size_t)(row0 + r) * PS2))[t] = x;
    }
}

// ---- Fixup kernel: verify guess against the true mask; repair mismatches ----
__global__ void __launch_bounds__(256)
fixup_kernel(const float* __restrict__ d, const int* __restrict__ poi_words,
             float* __restrict__ out) {
    __shared__ unsigned nz[32];           // combined true nonzero mask
    __shared__ unsigned mism[32];         // mismatch bitmap vs guess
    __shared__ int      sh_any, sh_odd, sh_last;
    __shared__ int      spoi[PS2];

    const int t = threadIdx.x;            // 0..255
    const int g = blockIdx.x;             // 0..63

    if (t == 0) { sh_any = 0; sh_odd = 0; sh_last = 0; }
    __syncthreads();
    if (t < 32) {
        unsigned x = 0;
#pragma unroll
        for (int k = 0; k < NSHARD; k++)
            x |= ((const volatile unsigned*)g_maskpad)[((k * 32 + t) << 6)];
        nz[t] = x;
        // guess: empty iff cell even; actual empty iff nz bit 0.
        // mismatch = (~nz) ^ evenbits(0x55555555) = nz ^ 0xAAAAAAAA
        const unsigned mm = x ^ 0xAAAAAAAAu;
        mism[t] = mm;
        if (mm) atomicOr(&sh_any, 1);
    }
    __syncthreads();

    if (sh_any) {                         // slow path: exact repair (rare/never)
        // decode poi into smem
        const int4 w = ((const int4*)poi_words)[t];
        if (w.y | w.w) atomicOr(&sh_odd, 1);
        __syncthreads();
        if (sh_odd) {
            ((int4*)spoi)[t] = w;
        } else {
            const int4 p0 = ((const int4*)poi_words)[2 * t];
            const int4 p1 = ((const int4*)poi_words)[2 * t + 1];
            ((int4*)spoi)[t] = make_int4(p0.x, p0.z, p1.x, p1.z);
        }
        __syncthreads();

        // this block repairs rows [g*64, g*64+64); threads t<64 take one row each
        if (t < 64) {
            const int R = g * 64 + t;
            const int b = R >> 6, c = R & 63;
            const float* drow = d + ((size_t)(b * PT + (PT - 1)) * PC + c) * PS2;
            float* orow = out + (size_t)R * PS2;
            for (int s = 0; s < PS2; s++) {
                if ((mism[s >> 5] >> (s & 31)) & 1u) {
                    const bool empty = !((nz[s >> 5] >> (s & 31)) & 1u);
                    orow[s] = drow[s] + (empty ? drow[spoi[s]] : 0.0f);
                }
            }
        }
    }

    // epilogue: last block re-zeroes shards + counter for the next replay
    if (t == 0) {
        __threadfence();
        if (atomicAdd(&g_c1, 1) == GRIDF - 1) sh_last = 1;
    }
    __syncthreads();
    if (sh_last) {
        for (int i = t; i < NSHARD * 32; i += 256) g_maskpad[i << 6] = 0;
        if (t == 0) { g_c1 = 0; __threadfence(); }
    }
}

extern "C" void kernel_launch(void* const* d_in, const int* in_sizes, int n_in,
                              void* d_out, int out_size) {
    const float* d   = (const float*)d_in[0];
    const int*   m   = (const int*)d_in[1];
    const int*   poi = (const int*)d_in[2];   // int32 or int64 words, auto-detected
    // d_in[3] = side (constant 32), unused.
    float* out = (float*)d_out;

    main_kernel<<<GRIDM, 256>>>(d, m, poi, out);
    fixup_kernel<<<GRIDF, 256>>>(d, poi, out);
}

// round 16
// speedup vs baseline: 1.3375x; 1.1800x over previous
#include <cuda_runtime.h>
#include <cuda_bf16.h>
#include <cstdint>

// Problem constants (fixed by the dataset): B=64, T=12, C=64, SIDE=32, S2=1024.
#define PB   64
#define PT   12
#define PC   64
#define PS2  1024
#define ROWS (PB * PC)            // 4096 (b,c) rows in the last-T slice

#define RPB    8                  // rows per block
#define GRIDM  (ROWS / RPB)       // 512 blocks
#define NSHARD 16                 // mask atomic shards (512/16 = 32 RMW per address)

// Persistent scratch (module-load zeroed; the last-arriving block re-zeroes it
// each launch => every call identical => graph-replay deterministic).
__device__ unsigned g_maskpad[NSHARD * 32 * 64];  // word (k,i) at (k*32+i)*64
__device__ int      g_c1;                         // completion counter

// Speculative apply + true-mask reduce + last-block verification/repair.
//   guess:  cell s is empty  <=>  s even   (forced by reference's cell_keep)
//   out[row,s] = d[row,s] + (s even ? d[row,poi[s]] : 0)   written immediately
//   true mask published to shards; LAST block verifies, repairs if ever wrong.
__global__ void __launch_bounds__(256, 4)
main_kernel(const float* __restrict__ d, const int* __restrict__ m,
            const int* __restrict__ poi_words, float* __restrict__ out) {
    __shared__ float    rs[RPB][PS2];     // 32 KB staged d rows
    __shared__ unsigned smask[32];        // block-partial 1024-bit nonzero mask
    __shared__ int      sh_odd, sh_last;
    __shared__ unsigned nz[32];           // (tail) combined true mask

    const int t = threadIdx.x;            // 0..255
    const int g = blockIdx.x;             // 0..511
    const int row0 = g * RPB;
    const int b  = row0 >> 6;
    const int cc = row0 & 63;
    const size_t base = ((size_t)(b * PT + (PT - 1)) * PC + cc) * PS2;

    if (t == 0) { sh_odd = 0; sh_last = 0; }
    if (t < 32) smask[t] = 0;

    // ---- TRUE mask reduce over this block's 8 m rows (cells 4t..4t+3) ----
    const int* msrc = m + base;
    int4 acc = make_int4(0, 0, 0, 0);
#pragma unroll
    for (int r = 0; r < RPB; r++) {
        const int4 v = *(const int4*)(msrc + r * PS2 + 4 * t);
        acc.x |= v.x; acc.y |= v.y; acc.z |= v.z; acc.w |= v.w;
    }

    // ---- poi decode (every block; dtype auto-detect: JAX silently narrows
    // jnp.int64 -> int32). First 1024 words safe for both dtypes; int64
    // little-endian with values < 1024 => all odd words zero.
    const int4 w  = ((const int4*)poi_words)[t];
    const int4 p0 = ((const int4*)poi_words)[2 * t];
    const int4 p1 = ((const int4*)poi_words)[2 * t + 1];
    if (w.y | w.w) atomicOr(&sh_odd, 1);

    // ---- stage this block's 8 d rows into smem ----
    const float* dsrc = d + base;
    float4 v[RPB];
#pragma unroll
    for (int r = 0; r < RPB; r++)
        v[r] = *(const float4*)(dsrc + r * PS2 + 4 * t);
#pragma unroll
    for (int r = 0; r < RPB; r++)
        ((float4*)rs[r])[t] = v[r];

    __syncthreads();                      // rs staged, sh_odd + smask ready
    const int4 pi = sh_odd ? w : make_int4(p0.x, p0.z, p1.x, p1.z);

    const unsigned nib = (acc.x ? 1u : 0u) | (acc.y ? 2u : 0u)
                       | (acc.z ? 4u : 0u) | (acc.w ? 8u : 0u);
    if (nib) atomicOr(&smask[t >> 3], nib << ((t & 7) * 4));
    __syncthreads();                      // smask final
    if (t < 32 && smask[t])
        atomicOr(&g_maskpad[(((g & (NSHARD - 1)) * 32 + t) << 6)], smask[t]);

    // ---- speculative output: even cells (4t, 4t+2) get the compensation ----
#pragma unroll
    for (int r = 0; r < RPB; r++) {
        float4 x = v[r];
        x.x += rs[r][pi.x];               // cell 4t   (even -> guessed empty)
        x.z += rs[r][pi.z];               // cell 4t+2 (even -> guessed empty)
        ((float4*)(out + (size_t)(row0 + r) * PS2))[t] = x;
    }

    // ---- completion: last-arriving block verifies the guess ----
    if (t == 0) {
        __threadfence();                  // publish stores + shard flushes
        if (atomicAdd(&g_c1, 1) == GRIDM - 1) sh_last = 1;
    }
    __syncthreads();
    if (!sh_last) return;

    // ======== TAIL (one block; all other blocks' work already visible) ======
    __threadfence();                      // acquire
    if (t < 32) {
        unsigned x = 0;
#pragma unroll
        for (int k = 0; k < NSHARD; k++)
            x |= ((const volatile unsigned*)g_maskpad)[((k * 32 + t) << 6)];
        nz[t] = x;
    }
    __syncthreads();
    // guess says: empty == even cell. actual: empty == (nz bit 0).
    // mismatch bit = nz[s] XOR (s odd)  ->  word-wise: nz ^ 0xAAAAAAAA
    const unsigned mm = (t < 32) ? (nz[t] ^ 0xAAAAAAAAu) : 0u;
    __shared__ int sh_any;
    if (t == 0) sh_any = 0;
    __syncthreads();
    if (mm) atomicOr(&sh_any, 1);
    __syncthreads();

    if (sh_any) {
        // slow path (never taken for this distribution; correctness insurance):
        // repair every mismatched cell of every row straight from d.
        __shared__ unsigned mismw[32];
        if (t < 32) mismw[t] = nz[t] ^ 0xAAAAAAAAu;
        __syncthreads();
        for (int R = 0; R < ROWS; R++) {
            const int bb = R >> 6, c = R & 63;
            const float* drow = d + ((size_t)(bb * PT + (PT - 1)) * PC + c) * PS2;
            float* orow = out + (size_t)R * PS2;
            for (int s = t; s < PS2; s += 256) {
                if ((mismw[s >> 5] >> (s & 31)) & 1u) {
                    const bool empty = !((nz[s >> 5] >> (s & 31)) & 1u);
                    orow[s] = drow[s] + (empty ? drow[pi.x * 0 +  // keep pi live
                                                     ((const volatile int*)0 == nullptr ?
                                                      0 : 0)] : 0.0f);
                }
            }
        }
        // NOTE: the repair above needs poi; recompute it here properly.
        __shared__ int spoi[PS2];
        {
            const int4 q0 = ((const int4*)poi_words)[2 * t];
            const int4 q1 = ((const int4*)poi_words)[2 * t + 1];
            ((int4*)spoi)[t] = sh_odd ? ((const int4*)poi_words)[t]
                                      : make_int4(q0.x, q0.z, q1.x, q1.z);
        }
        __syncthreads();
        for (int R = 0; R < ROWS; R++) {
            const int bb = R >> 6, c = R & 63;
            const float* drow = d + ((size_t)(bb * PT + (PT - 1)) * PC + c) * PS2;
            float* orow = out + (size_t)R * PS2;
            for (int s = t; s < PS2; s += 256) {
                if ((mismw[s >> 5] >> (s & 31)) & 1u) {
                    const bool empty = !((nz[s >> 5] >> (s & 31)) & 1u);
                    orow[s] = drow[s] + (empty ? drow[spoi[s]] : 0.0f);
                }
            }
        }
    }

    // reset scratch for the next (graph) replay
    for (int i = t; i < NSHARD * 32; i += 256) g_maskpad[i << 6] = 0;
    if (t == 0) { g_c1 = 0; __threadfence(); }
}

extern "C" void kernel_launch(void* const* d_in, const int* in_sizes, int n_in,
                              void* d_out, int out_size) {
    const float* d   = (const float*)d_in[0];
    const int*   m   = (const int*)d_in[1];
    const int*   poi = (const int*)d_in[2];   // int32 or int64 words, auto-detected
    // d_in[3] = side (constant 32), unused.
    float* out = (float*)d_out;

    main_kernel<<<GRIDM, 256>>>(d, m, poi, out);
}